// round 16
// baseline (speedup 1.0000x reference)
#include <cuda_runtime.h>
#include <cstdint>

// Fixed shapes: B=16, K=64, H=96, W=96
constexpr int B = 16;
constexpr int K = 64;
constexpr int H = 96;
constexpr int W = 96;
constexpr int IMG = H * W;                      // 9216
constexpr int NSTACK = B * K;                   // 1024
constexpr int NIMG = 2 * NSTACK;                // 2048 images (both stacks)
constexpr long long NBIG = (long long)B * K * H * W;
constexpr int KP_ELEMS = B * 3 * K * 2;         // 6144
constexpr int ZETA_ELEMS = B * K;               // 1024

constexpr int THREADS = 256;                    // 8 warps
constexpr int PARTS = 3;                        // 3 tile-blocks per image
constexpr int TILE_ROWS  = H / PARTS;           // 32
constexpr int TILE_ELEMS = TILE_ROWS * W;       // 3072 floats
constexpr int TILE_BYTES = TILE_ELEMS * 4;      // 12288 B
constexpr int TILE_V4    = TILE_ELEMS / 4;      // 768 float4
constexpr int ITERS = TILE_V4 / THREADS;        // 3
constexpr int NTILE = NIMG * PARTS;             // 6144 blocks

// Cross-block combine scratch (device globals — no allocation).
// g_cnt self-resets to 0 each use => deterministic across graph replays.
__device__ float g_part[NIMG][PARTS][3];        // (z, fx, fy) per part
__device__ unsigned int g_cnt[NIMG];            // zero-initialized at load

// sigmoid with div.approx (MUFU.RCP + FMUL); rel err ~2e-7 << 1e-3 gate
__device__ __forceinline__ float sigmoidf(float x) {
    return __fdividef(1.0f, 1.0f + __expf(-x));
}

// mbarrier wait with HW sleep hint
__device__ __forceinline__ void mbar_wait(uint32_t msa, uint32_t parity) {
    uint32_t done;
    asm volatile(
        "{\n\t.reg .pred p;\n\t"
        "mbarrier.try_wait.parity.acquire.cta.shared::cta.b64 p, [%1], %2;\n\t"
        "selp.b32 %0, 1, 0, p;\n\t}"
        : "=r"(done) : "r"(msa), "r"(parity) : "memory");
    if (!done) {
        asm volatile(
            "{\n\t.reg .pred P1;\n\t"
            "WAIT_LOOP_%=:\n\t"
            "mbarrier.try_wait.parity.acquire.cta.shared::cta.b64 P1, [%0], %1, 0x989680;\n\t"
            "@P1 bra.uni WAIT_DONE_%=;\n\t"
            "bra.uni WAIT_LOOP_%=;\n\t"
            "WAIT_DONE_%=:\n\t}"
            :: "r"(msa), "r"(parity) : "memory");
    }
}

__global__ __launch_bounds__(THREADS)
void fused_decode_kernel(const float* __restrict__ Rk,
                         const float* __restrict__ tfRk,
                         float* __restrict__ Dk_out,
                         float* __restrict__ tfDk_out,
                         float* __restrict__ kp_out,
                         float* __restrict__ tfkp_out,
                         float* __restrict__ zeta_out,
                         float* __restrict__ tfzeta_out)
{
    __shared__ alignas(128) float tile[TILE_ELEMS];   // 12 KB
    __shared__ alignas(8) unsigned long long mbar;
    __shared__ float sm0[8], smx[8], smy[8];

    const int t = blockIdx.x;                  // 0..6143
    const int img = t / PARTS;                 // 0..2047
    const int part = t - img * PARTS;          // 0..2
    const int which = img >> 10;               // 0 = Rk, 1 = tf_Rk
    const int stack = img & (NSTACK - 1);

    const float* __restrict__ Rimg = (which ? tfRk : Rk) + (size_t)stack * IMG;
    float* __restrict__ Dimg       = (which ? tfDk_out : Dk_out) + (size_t)stack * IMG;

    const int tid = threadIdx.x;
    const int lane = tid & 31;
    const int warp = tid >> 5;

    if (tid == 0) {
        const uint32_t msa = (uint32_t)__cvta_generic_to_shared(&mbar);
        asm volatile("mbarrier.init.shared.b64 [%0], %1;" :: "r"(msa), "r"(1) : "memory");
    }
    __syncthreads();

    // L2 policies: input reads evict_first, output writes evict_last
    // (write-only output rewritten every replay -> stays resident in L2).
    uint64_t pol_ef, pol_el;
    asm volatile("createpolicy.fractional.L2::evict_first.b64 %0, 1.0;" : "=l"(pol_ef));
    asm volatile("createpolicy.fractional.L2::evict_last.b64 %0, 1.0;"  : "=l"(pol_el));

    // One 12 KB TMA load for this tile
    if (tid == 0) {
        const uint32_t msa = (uint32_t)__cvta_generic_to_shared(&mbar);
        const uint32_t bsa = (uint32_t)__cvta_generic_to_shared(tile);
        const float* src = Rimg + part * TILE_ELEMS;
        asm volatile("mbarrier.arrive.expect_tx.shared.b64 _, [%0], %1;"
                     :: "r"(msa), "r"(TILE_BYTES) : "memory");
        asm volatile("cp.async.bulk.shared::cta.global.mbarrier::complete_tx::bytes.L2::cache_hint "
                     "[%0], [%1], %2, [%3], %4;"
                     :: "r"(bsa), "l"(src), "r"(TILE_BYTES), "r"(msa), "l"(pol_ef)
                     : "memory");
    }
    mbar_wait((uint32_t)__cvta_generic_to_shared(&mbar), 0u);

    // ---- sigmoid in place + moments ----
    float4* __restrict__ T4 = reinterpret_cast<float4*>(tile);
    float s0 = 0.0f, sx = 0.0f, sy = 0.0f;

#pragma unroll
    for (int it = 0; it < ITERS; ++it) {
        const int v = tid + it * THREADS;      // float4 index within tile [0,768)
        float4 r = T4[v];
        float4 d;
        d.x = sigmoidf(r.x);
        d.y = sigmoidf(r.y);
        d.z = sigmoidf(r.z);
        d.w = sigmoidf(r.w);
        T4[v] = d;                             // sigmoid in place (STS)

        const int e = v * 4;
        const int hl = e / W;                  // local row within tile
        const int w = e - hl * W;
        const int h = hl + part * TILE_ROWS;   // global row
        const float rowsum = (d.x + d.y) + (d.z + d.w);
        s0 += rowsum;
        sy += rowsum * (float)h;
        sx += fmaf((float)w, rowsum, fmaf(3.0f, d.w, fmaf(2.0f, d.z, d.y)));
    }

    __syncthreads();                           // tile fully sigmoided in smem

    // Bulk TMA store of the sigmoided tile (async, evict_last pin)
    if (tid == 0) {
        const uint32_t bsa = (uint32_t)__cvta_generic_to_shared(tile);
        asm volatile("fence.proxy.async.shared::cta;" ::: "memory");
        asm volatile("cp.async.bulk.global.shared::cta.bulk_group.L2::cache_hint "
                     "[%0], [%1], %2, %3;"
                     :: "l"(Dimg + part * TILE_ELEMS), "r"(bsa), "r"(TILE_BYTES), "l"(pol_el)
                     : "memory");
        asm volatile("cp.async.bulk.commit_group;" ::: "memory");
    }

    // ---- block reduction of this tile's partial moments ----
#pragma unroll
    for (int o = 16; o > 0; o >>= 1) {
        s0 += __shfl_down_sync(0xffffffffu, s0, o);
        sx += __shfl_down_sync(0xffffffffu, sx, o);
        sy += __shfl_down_sync(0xffffffffu, sy, o);
    }
    if (lane == 0) { sm0[warp] = s0; smx[warp] = sx; smy[warp] = sy; }
    __syncthreads();

    if (tid == 0) {
        float z = 0.0f, fx = 0.0f, fy = 0.0f;
#pragma unroll
        for (int i = 0; i < 8; ++i) { z += sm0[i]; fx += smx[i]; fy += smy[i]; }

        // Publish this part's partial sums, then signal.
        g_part[img][part][0] = z;
        g_part[img][part][1] = fx;
        g_part[img][part][2] = fy;

        // Drain our bulk store before exiting (also before signaling).
        asm volatile("cp.async.bulk.wait_group 0;" ::: "memory");
        __threadfence();
        const unsigned old = atomicAdd(&g_cnt[img], 1u);

        if (old == PARTS - 1) {
            // Last arriver: all partials visible (their fences precede the atomic).
            __threadfence();
            float zt = 0.0f, fxt = 0.0f, fyt = 0.0f;
#pragma unroll
            for (int p = 0; p < PARTS; ++p) {   // fixed order -> deterministic
                zt  += g_part[img][p][0];
                fxt += g_part[img][p][1];
                fyt += g_part[img][p][2];
            }

            // Full-precision div: feeds rintf (round-half-even = jnp.round)
            const float kx = rintf(fxt / zt);
            const float ky = rintf(fyt / zt);
            const int wi = (int)kx;
            const int hi = (int)ky;

            // dloc from the READ-ONLY input (no cross-block store ordering
            // hazard), recomputing the same approx sigmoid stored in Dk.
            const float dloc = sigmoidf(__ldg(&Rimg[hi * W + wi]));

            const int b = stack / K;
            const int k = stack - b * K;
            float* kp_base   = (which ? tfkp_out : kp_out);
            float* zeta_base = (which ? tfzeta_out : zeta_out);

            float* kp  = kp_base + ((size_t)b * (3 * K) + k) * 2;
            float* kp1 = kp_base + ((size_t)b * (3 * K) + K + k) * 2;
            float* kp2 = kp_base + ((size_t)b * (3 * K) + 2 * K + k) * 2;
            kp[0]  = kx;
            kp[1]  = ky;
            kp1[0] = truncf(kx + kx * dloc);
            kp1[1] = truncf(ky + ky * dloc);
            kp2[0] = truncf(kx - kx * dloc);
            kp2[1] = truncf(ky - ky * dloc);

            zeta_base[stack] = zt;

            g_cnt[img] = 0;                     // reset for next graph replay
        }
    }
}

extern "C" void kernel_launch(void* const* d_in, const int* in_sizes, int n_in,
                              void* d_out, int out_size)
{
    const float* Rk   = (const float*)d_in[0];
    const float* tfRk = (const float*)d_in[1];

    float* out = (float*)d_out;
    float* Dk     = out;
    float* tfDk   = out + NBIG;
    float* kp     = out + 2 * NBIG;
    float* tfkp   = kp + KP_ELEMS;
    float* zeta   = tfkp + KP_ELEMS;
    float* tfzeta = zeta + ZETA_ELEMS;

    fused_decode_kernel<<<NTILE, THREADS>>>(Rk, tfRk, Dk, tfDk,
                                            kp, tfkp, zeta, tfzeta);
}